// round 1
// baseline (speedup 1.0000x reference)
#include <cuda_runtime.h>

// Problem constants
#define NQ     131072      // B*H*W = 32*64*64
#define CDIM   64
#define KCODES 1024
#define QTOT   8388608     // 32*64*64*64 quantized elements
#define MT     128         // queries per block
#define NBLK   (NQ / MT)   // 1024 blocks

// Scratch (no allocations allowed)
__device__ float g_nhn[KCODES];       // -0.5 * ||e_k||^2
__device__ float g_partials[8192];    // per-block loss partials

// ---------------- f32x2 packed helpers (Blackwell) ----------------
__device__ __forceinline__ unsigned long long pk2(float lo, float hi) {
    unsigned long long r;
    asm("mov.b64 %0, {%1, %2};" : "=l"(r) : "f"(lo), "f"(hi));
    return r;
}
__device__ __forceinline__ void fma2(unsigned long long &d,
                                     unsigned long long a, unsigned long long b) {
    asm("fma.rn.f32x2 %0, %1, %2, %0;" : "+l"(d) : "l"(a), "l"(b));
}
__device__ __forceinline__ void unpk2(float &lo, float &hi, unsigned long long v) {
    asm("mov.b64 {%0, %1}, %2;" : "=f"(lo), "=f"(hi) : "l"(v));
}

// ---------------- Kernel A: code norms ----------------
__global__ void enorm_kernel(const float* __restrict__ emb) {
    int k = blockIdx.x * blockDim.x + threadIdx.x;
    if (k < KCODES) {
        const float4* r = (const float4*)(emb + k * CDIM);
        float s = 0.f;
        #pragma unroll
        for (int i = 0; i < 16; i++) {
            float4 v = r[i];
            s += v.x * v.x + v.y * v.y + v.z * v.z + v.w * v.w;
        }
        g_nhn[k] = -0.5f * s;
    }
}

// ---------------- Kernel B: fused distance-GEMM + argmax ----------------
// Block: 256 threads = (16 tx) x (16 ty). Tile: 128 queries x 128 codes.
// Thread micro-tile: 8 queries x 8 codes, codes packed in f32x2 pairs.
// smem: xs[64][128] (32KB) + es[64][128] (32KB) + nhn_s[1024] (4KB) = 68KB dynamic.
extern "C" __global__ void __launch_bounds__(256, 2)
argmin_kernel(const float* __restrict__ x, const float* __restrict__ emb,
              float* __restrict__ idx_out) {
    extern __shared__ float smem[];
    float* xs    = smem;          // [c][q] transposed
    float* es    = smem + 8192;   // [c][k] transposed
    float* nhn_s = smem + 16384;  // [1024]

    int tid = threadIdx.x;
    int tx = tid & 15, ty = tid >> 4;
    int q0 = blockIdx.x * MT;

    for (int i = tid; i < KCODES; i += 256) nhn_s[i] = g_nhn[i];

    // Load + transpose x tile: x is [B,C,H,W]; queries are contiguous in HW for
    // fixed (b,c). q0 is a multiple of 128, 4096 % 128 == 0, so one batch item.
    const float* xbase = x + (q0 >> 12) * (CDIM * 4096) + (q0 & 4095);
    {
        int i4 = tid & 31;     // float4 column within row (q/4)
        int cb = tid >> 5;     // 0..7
        #pragma unroll
        for (int it = 0; it < 8; it++) {
            int c = cb + it * 8;
            float4 v = *(const float4*)(xbase + c * 4096 + i4 * 4);
            *(float4*)(xs + c * 128 + i4 * 4) = v;
        }
    }

    unsigned long long acc[8][4];
    float best[8];
    int   bidx[8];
    #pragma unroll
    for (int i = 0; i < 8; i++) { best[i] = -3.0e38f; bidx[i] = 0; }

    const float4* emb4 = (const float4*)emb;

    for (int kt = 0; kt < 8; kt++) {
        __syncthreads();
        // Load + transpose e tile: es[c][k] = emb[kt*128+k][c].
        {
            int k  = tid & 127;
            int cg = tid >> 7;  // 0..1
            #pragma unroll
            for (int it = 0; it < 8; it++) {
                int c4 = cg * 8 + it;
                float4 v = emb4[(kt * 128 + k) * 16 + c4];
                es[(c4 * 4 + 0) * 128 + k] = v.x;
                es[(c4 * 4 + 1) * 128 + k] = v.y;
                es[(c4 * 4 + 2) * 128 + k] = v.z;
                es[(c4 * 4 + 3) * 128 + k] = v.w;
            }
        }
        __syncthreads();

        #pragma unroll
        for (int qi = 0; qi < 8; qi++)
            #pragma unroll
            for (int kp = 0; kp < 4; kp++) acc[qi][kp] = 0ULL;

        #pragma unroll 8
        for (int c = 0; c < 64; c++) {
            const float4* xr = (const float4*)(xs + c * 128);
            const float4* er = (const float4*)(es + c * 128);
            float4 xa = xr[ty],      xb = xr[16 + ty];
            float4 ea = er[tx],      eb = er[16 + tx];
            unsigned long long ep[4] = { pk2(ea.x, ea.y), pk2(ea.z, ea.w),
                                         pk2(eb.x, eb.y), pk2(eb.z, eb.w) };
            unsigned long long xq[8] = { pk2(xa.x, xa.x), pk2(xa.y, xa.y),
                                         pk2(xa.z, xa.z), pk2(xa.w, xa.w),
                                         pk2(xb.x, xb.x), pk2(xb.y, xb.y),
                                         pk2(xb.z, xb.z), pk2(xb.w, xb.w) };
            #pragma unroll
            for (int qi = 0; qi < 8; qi++)
                #pragma unroll
                for (int kp = 0; kp < 4; kp++)
                    fma2(acc[qi][kp], xq[qi], ep[kp]);
        }

        // Fold -0.5||e||^2 and update running argmax (k visited ascending).
        int kb = kt * 128;
        #pragma unroll
        for (int kp = 0; kp < 4; kp++) {
            int klocal = (kp < 2) ? (tx * 4 + kp * 2) : (64 + tx * 4 + (kp - 2) * 2);
            float n0 = nhn_s[kb + klocal];
            float n1 = nhn_s[kb + klocal + 1];
            #pragma unroll
            for (int qi = 0; qi < 8; qi++) {
                float lo, hi;
                unpk2(lo, hi, acc[qi][kp]);
                float s0 = lo + n0, s1 = hi + n1;
                if (s0 > best[qi]) { best[qi] = s0; bidx[qi] = kb + klocal; }
                if (s1 > best[qi]) { best[qi] = s1; bidx[qi] = kb + klocal + 1; }
            }
        }
    }

    // Cross-thread (tx) reduction per query; reuse xs region.
    __syncthreads();
    float* rs = smem;                 // [128][16]
    int*   rk = (int*)(smem + 2048);  // [128][16]
    #pragma unroll
    for (int qi = 0; qi < 8; qi++) {
        int q = (qi < 4) ? (ty * 4 + qi) : (64 + ty * 4 + (qi - 4));
        rs[q * 16 + tx] = best[qi];
        rk[q * 16 + tx] = bidx[qi];
    }
    __syncthreads();
    if (tid < 128) {
        int q = tid;
        float b = rs[q * 16];
        int  bk = rk[q * 16];
        #pragma unroll
        for (int t = 1; t < 16; t++) {
            float s = rs[q * 16 + t];
            int  k2 = rk[q * 16 + t];
            if (s > b || (s == b && k2 < bk)) { b = s; bk = k2; }
        }
        idx_out[q0 + q] = (float)bk;
    }
}

// ---------------- Kernel C: gather quantized + loss partials ----------------
// 2M threads: each handles one (n, 4 consecutive c). Coalesced along n.
__global__ void gather_kernel(const float* __restrict__ x,
                              const float* __restrict__ emb,
                              const float* __restrict__ idx_f,
                              float* __restrict__ outq) {
    int t  = blockIdx.x * 256 + threadIdx.x;   // 0 .. 2097151
    int n  = t & (NQ - 1);
    int c0 = (t >> 17) << 2;                   // (t / 131072) * 4
    int id = (int)idx_f[n];
    float4 ev = ((const float4*)emb)[id * 16 + (c0 >> 2)];
    int b = n >> 12, hw = n & 4095;
    int base = (b * 64 + c0) * 4096 + hw;
    float evs[4] = {ev.x, ev.y, ev.z, ev.w};
    float le = 0.f;
    #pragma unroll
    for (int j = 0; j < 4; j++) {
        int f = base + j * 4096;
        float xv = x[f];
        float d = evs[j] - xv;
        le += d * d;
        outq[f] = evs[j];     // straight-through output == quantized values
    }
    // Deterministic block reduction (no atomics)
    __shared__ float red[8];
    #pragma unroll
    for (int o = 16; o > 0; o >>= 1) le += __shfl_down_sync(0xffffffffu, le, o);
    if ((threadIdx.x & 31) == 0) red[threadIdx.x >> 5] = le;
    __syncthreads();
    if (threadIdx.x == 0) {
        float s = 0.f;
        #pragma unroll
        for (int w = 0; w < 8; w++) s += red[w];
        g_partials[blockIdx.x] = s;
    }
}

// ---------------- Kernel D: final deterministic loss reduce ----------------
__global__ void loss_kernel(float* __restrict__ out_loss) {
    __shared__ float sm[256];
    float s = 0.f;
    for (int i = threadIdx.x; i < 8192; i += 256) s += g_partials[i];
    sm[threadIdx.x] = s;
    __syncthreads();
    for (int o = 128; o > 0; o >>= 1) {
        if (threadIdx.x < o) sm[threadIdx.x] += sm[threadIdx.x + o];
        __syncthreads();
    }
    if (threadIdx.x == 0) out_loss[0] = 0.25f * sm[0] / 8388608.0f;
}

// ---------------- Launch ----------------
extern "C" void kernel_launch(void* const* d_in, const int* in_sizes, int n_in,
                              void* d_out, int out_size) {
    const float* x   = (const float*)d_in[0];
    const float* emb = (const float*)d_in[1];
    // Defensive input-order check (x has 8388608 elems, embedding 65536)
    if (n_in >= 2 && in_sizes[0] == KCODES * CDIM) {
        const float* t = x; x = emb; emb = t;
    }

    float* out      = (float*)d_out;
    float* out_loss = out;                 // [1]
    float* out_q    = out + 1;             // [8388608] in (B,C,H,W) order
    float* out_idx  = out + 1 + QTOT;      // [131072] indices as float

    const int SMEM_BYTES = (8192 + 8192 + 1024) * (int)sizeof(float);  // 68 KB
    cudaFuncSetAttribute((const void*)argmin_kernel,
                         cudaFuncAttributeMaxDynamicSharedMemorySize, SMEM_BYTES);

    enorm_kernel<<<4, 256>>>(emb);
    argmin_kernel<<<NBLK, 256, SMEM_BYTES>>>(x, emb, out_idx);
    gather_kernel<<<8192, 256>>>(x, emb, out_idx, out_q);
    loss_kernel<<<1, 256>>>(out_loss);
}

// round 5
// speedup vs baseline: 1.0709x; 1.0709x over previous
#include <cuda_runtime.h>
#include <cstdint>

#define NQ     131072
#define CDIM   64
#define KCODES 1024
#define QTOT   8388608

__device__ float g_nhn[KCODES];
__device__ float g_partials[8192];

// ---------- smem layout (float offsets), total 206848 bytes ----------
#define A_OFF     0
#define A_SPLIT   16896          // 128 blocks * 132 floats per split
#define B_OFF     33792
#define B_SPLIT   4224           // 64 blocks * 66 floats per split
#define B_BUF     8448           // hi+lo per buffer
#define NHN_OFF   50688
#define SMEM_BYTES ((50688 + 1024) * 4)

__device__ __forceinline__ uint32_t tf32h(float x) {
    uint32_t r; asm("cvt.rna.tf32.f32 %0, %1;" : "=r"(r) : "f"(x)); return r;
}

__device__ __forceinline__ void mma8(float* c, const uint32_t* a, const uint32_t* b) {
    asm volatile("mma.sync.aligned.m16n8k8.row.col.f32.tf32.tf32.f32 "
        "{%0,%1,%2,%3}, {%4,%5,%6,%7}, {%8,%9}, {%0,%1,%2,%3};"
        : "+f"(c[0]), "+f"(c[1]), "+f"(c[2]), "+f"(c[3])
        : "r"(a[0]), "r"(a[1]), "r"(a[2]), "r"(a[3]), "r"(b[0]), "r"(b[1]));
}

// ---------------- Kernel A: -0.5*||e_k||^2 ----------------
__global__ void enorm_kernel(const float* __restrict__ emb) {
    int k = blockIdx.x * blockDim.x + threadIdx.x;
    if (k < KCODES) {
        const float4* r = (const float4*)(emb + k * CDIM);
        float s = 0.f;
        #pragma unroll
        for (int i = 0; i < 16; i++) {
            float4 v = r[i];
            s += v.x * v.x + v.y * v.y + v.z * v.z + v.w * v.w;
        }
        g_nhn[k] = -0.5f * s;
    }
}

// B chunk global load: per thread 8 float4, lanes stride 64 floats (L2-resident E)
__device__ __forceinline__ void ldgB(const float* __restrict__ emb, int k0, int t, float4* v) {
    int l = t & 31, w = t >> 5;
    #pragma unroll
    for (int it = 0; it < 8; it++) {
        int n  = l + 32 * (it & 1);
        int c4 = w * 4 + (it >> 1);
        v[it] = *(const float4*)(emb + (size_t)(k0 + n) * 64 + c4 * 4);
    }
}
// split tf32 hi/lo and store in mma-fragment order (padded blocks of 66 floats)
__device__ __forceinline__ void stsB(float* smB, int t, const float4* v) {
    int l = t & 31, w = t >> 5;
    #pragma unroll
    for (int it = 0; it < 8; it++) {
        int n  = l + 32 * (it & 1);
        int c4 = w * 4 + (it >> 1);
        float vv[4] = {v[it].x, v[it].y, v[it].z, v[it].w};
        #pragma unroll
        for (int j = 0; j < 4; j++) {
            int c = c4 * 4 + j;
            uint32_t h  = tf32h(vv[j]);
            uint32_t lo = tf32h(vv[j] - __uint_as_float(h));
            int off = ((c >> 3) * 8 + (n >> 3)) * 66 + ((n & 7) * 4 + j) * 2 + (c4 & 1);
            ((uint32_t*)smB)[off]           = h;
            ((uint32_t*)smB)[B_SPLIT + off] = lo;
        }
    }
}

// ---------------- Kernel B: tf32 3-pass mma.sync GEMM + fused argmin ----------------
// grid 512, block 128 (4 warps). CTA tile: 256 queries x 1024 codes (16 chunks of 64).
// Warp tile 64q x 64k. Accumulators: acc[4 m16][8 n8][4].
__global__ void __launch_bounds__(128, 1)
vq_mma_kernel(const float* __restrict__ x, const float* __restrict__ emb,
              float* __restrict__ idx_out) {
    extern __shared__ float sm[];
    int tid = threadIdx.x, wid = tid >> 5, lane = tid & 31;
    int gid = lane >> 2, tig = lane & 3;
    int q0 = blockIdx.x << 8;

    for (int i = tid; i < KCODES; i += 128) sm[NHN_OFF + i] = g_nhn[i];

    // A tile: 256q x 64c, tf32 hi/lo split, fragment-order smem.
    const float* xg = x + (size_t)(q0 >> 12) * (CDIM * 4096) + (q0 & 4095);
    #pragma unroll 4
    for (int it = 0; it < 32; it++) {
        int idx = tid + (it << 7);
        int f4 = idx & 63, c = idx >> 6;
        float4 v = *(const float4*)(xg + c * 4096 + f4 * 4);
        float vv[4] = {v.x, v.y, v.z, v.w};
        #pragma unroll
        for (int j = 0; j < 4; j++) {
            int q = f4 * 4 + j;
            uint32_t h  = tf32h(vv[j]);
            uint32_t lo = tf32h(vv[j] - __uint_as_float(h));
            int off = ((c >> 3) * 16 + (q >> 4)) * 132
                    + ((q & 7) * 4 + (c & 3)) * 4
                    + ((q & 15) >> 3) + 2 * ((c & 7) >> 2);
            ((uint32_t*)sm)[A_OFF + off]           = h;
            ((uint32_t*)sm)[A_OFF + A_SPLIT + off] = lo;
        }
    }

    float best[4][2];
    int   bidx[4][2];
    #pragma unroll
    for (int mi = 0; mi < 4; mi++) {
        best[mi][0] = best[mi][1] = -3.0e38f;
        bidx[mi][0] = bidx[mi][1] = 0;
    }

    float4 stage[8];
    ldgB(emb, 0, tid, stage);
    stsB(sm + B_OFF, tid, stage);
    __syncthreads();

    float acc[4][8][4];

    for (int ch = 0; ch < 16; ch++) {
        if (ch < 15) ldgB(emb, (ch + 1) * 64, tid, stage);

        #pragma unroll
        for (int mi = 0; mi < 4; mi++)
            #pragma unroll
            for (int ni = 0; ni < 8; ni++)
                #pragma unroll
                for (int j = 0; j < 4; j++) acc[mi][ni][j] = 0.f;

        const uint32_t* bufB = (const uint32_t*)(sm + B_OFF + (ch & 1) * B_BUF);

        #pragma unroll 1
        for (int p = 0; p < 3; p++) {
            const uint32_t* aB = (const uint32_t*)sm + A_OFF + ((p == 2) ? A_SPLIT : 0);
            const uint32_t* bB = bufB + ((p == 1) ? B_SPLIT : 0);
            #pragma unroll
            for (int ks = 0; ks < 8; ks++) {
                uint4 af[4];
                #pragma unroll
                for (int mi = 0; mi < 4; mi++)
                    af[mi] = *(const uint4*)(aB + (ks * 16 + wid * 4 + mi) * 132 + lane * 4);
                uint2 bf[8];
                #pragma unroll
                for (int ni = 0; ni < 8; ni++)
                    bf[ni] = *(const uint2*)(bB + (ks * 8 + ni) * 66 + lane * 2);
                #pragma unroll
                for (int mi = 0; mi < 4; mi++)
                    #pragma unroll
                    for (int ni = 0; ni < 8; ni++)
                        mma8(acc[mi][ni], (const uint32_t*)&af[mi], (const uint32_t*)&bf[ni]);
            }
        }

        // fold -0.5||e||^2, update running argmax (ascending k -> first-min tie-break)
        #pragma unroll
        for (int ni = 0; ni < 8; ni++) {
            float2 nn = *(const float2*)&sm[NHN_OFF + ch * 64 + ni * 8 + tig * 2];
            int col = ch * 64 + ni * 8 + tig * 2;
            #pragma unroll
            for (int mi = 0; mi < 4; mi++) {
                float s;
                s = acc[mi][ni][0] + nn.x; if (s > best[mi][0]) { best[mi][0] = s; bidx[mi][0] = col; }
                s = acc[mi][ni][1] + nn.y; if (s > best[mi][0]) { best[mi][0] = s; bidx[mi][0] = col + 1; }
                s = acc[mi][ni][2] + nn.x; if (s > best[mi][1]) { best[mi][1] = s; bidx[mi][1] = col; }
                s = acc[mi][ni][3] + nn.y; if (s > best[mi][1]) { best[mi][1] = s; bidx[mi][1] = col + 1; }
            }
        }

        if (ch < 15) stsB(sm + B_OFF + ((ch + 1) & 1) * B_BUF, tid, stage);
        __syncthreads();
    }

    // reduce across the 4 tig lanes sharing each query row
    #pragma unroll
    for (int mi = 0; mi < 4; mi++) {
        #pragma unroll
        for (int h = 0; h < 2; h++) {
            float s = best[mi][h];
            int   k = bidx[mi][h];
            #pragma unroll
            for (int off = 1; off <= 2; off <<= 1) {
                float so = __shfl_xor_sync(0xffffffffu, s, off);
                int   ko = __shfl_xor_sync(0xffffffffu, k, off);
                if (so > s || (so == s && ko < k)) { s = so; k = ko; }
            }
            if (tig == 0)
                idx_out[q0 + wid * 64 + mi * 16 + h * 8 + gid] = (float)k;
        }
    }
}

// ---------------- Kernel C: gather quantized + loss partials ----------------
__global__ void gather_kernel(const float* __restrict__ x,
                              const float* __restrict__ emb,
                              const float* __restrict__ idx_f,
                              float* __restrict__ outq) {
    int t  = blockIdx.x * 256 + threadIdx.x;
    int n  = t & (NQ - 1);
    int c0 = (t >> 17) << 2;
    int id = (int)idx_f[n];
    float4 ev = ((const float4*)emb)[id * 16 + (c0 >> 2)];
    int b = n >> 12, hw = n & 4095;
    int base = (b * 64 + c0) * 4096 + hw;
    float evs[4] = {ev.x, ev.y, ev.z, ev.w};
    float le = 0.f;
    #pragma unroll
    for (int j = 0; j < 4; j++) {
        int f = base + j * 4096;
        float xv = x[f];
        float d = evs[j] - xv;
        le += d * d;
        outq[f] = evs[j];
    }
    __shared__ float red[8];
    #pragma unroll
    for (int o = 16; o > 0; o >>= 1) le += __shfl_down_sync(0xffffffffu, le, o);
    if ((threadIdx.x & 31) == 0) red[threadIdx.x >> 5] = le;
    __syncthreads();
    if (threadIdx.x == 0) {
        float s = 0.f;
        #pragma unroll
        for (int w = 0; w < 8; w++) s += red[w];
        g_partials[blockIdx.x] = s;
    }
}

// ---------------- Kernel D: final deterministic loss reduce ----------------
__global__ void loss_kernel(float* __restrict__ out_loss) {
    __shared__ float smr[256];
    float s = 0.f;
    for (int i = threadIdx.x; i < 8192; i += 256) s += g_partials[i];
    smr[threadIdx.x] = s;
    __syncthreads();
    for (int o = 128; o > 0; o >>= 1) {
        if (threadIdx.x < o) smr[threadIdx.x] += smr[threadIdx.x + o];
        __syncthreads();
    }
    if (threadIdx.x == 0) out_loss[0] = 0.25f * smr[0] / 8388608.0f;
}

// ---------------- Launch ----------------
extern "C" void kernel_launch(void* const* d_in, const int* in_sizes, int n_in,
                              void* d_out, int out_size) {
    const float* x   = (const float*)d_in[0];
    const float* emb = (const float*)d_in[1];
    if (n_in >= 2 && in_sizes[0] == KCODES * CDIM) {
        const float* t = x; x = emb; emb = t;
    }

    float* out      = (float*)d_out;
    float* out_loss = out;
    float* out_q    = out + 1;
    float* out_idx  = out + 1 + QTOT;

    cudaFuncSetAttribute((const void*)vq_mma_kernel,
                         cudaFuncAttributeMaxDynamicSharedMemorySize, SMEM_BYTES);

    enorm_kernel<<<4, 256>>>(emb);
    vq_mma_kernel<<<NQ / 256, 128, SMEM_BYTES>>>(x, emb, out_idx);
    gather_kernel<<<8192, 256>>>(x, emb, out_idx, out_q);
    loss_kernel<<<1, 256>>>(out_loss);
}

// round 6
// speedup vs baseline: 1.1799x; 1.1017x over previous
#include <cuda_runtime.h>
#include <cstdint>

#define NQ     131072
#define CDIM   64
#define KCODES 1024
#define QTOT   8388608

__device__ float g_nhn[KCODES];
__device__ float g_partials[8192];
__device__ float g_Bh[65536];   // codebook hi split, fragment order, 16 chunks * 4096
__device__ float g_Bl[65536];   // codebook lo split

// ---- smem layout (bytes): lo-tile [q][68] | B ring 4*32KB | nhn ----
#define SM_LO   0
#define SM_B    69632
#define SM_NHN  200704
#define SMEM_BYTES 204800

__device__ __forceinline__ uint32_t tf32h(float x) {
    uint32_t r; asm("cvt.rna.tf32.f32 %0, %1;" : "=r"(r) : "f"(x)); return r;
}
__device__ __forceinline__ float tf32f(float x) {
    return __uint_as_float(tf32h(x));
}
__device__ __forceinline__ void mma8(float* c, const uint32_t* a, const uint32_t* b) {
    asm volatile("mma.sync.aligned.m16n8k8.row.col.f32.tf32.tf32.f32 "
        "{%0,%1,%2,%3}, {%4,%5,%6,%7}, {%8,%9}, {%0,%1,%2,%3};"
        : "+f"(c[0]), "+f"(c[1]), "+f"(c[2]), "+f"(c[3])
        : "r"(a[0]), "r"(a[1]), "r"(a[2]), "r"(a[3]), "r"(b[0]), "r"(b[1]));
}
__device__ __forceinline__ void cp16(uint32_t dst, const void* src) {
    asm volatile("cp.async.cg.shared.global [%0], [%1], 16;" :: "r"(dst), "l"(src) : "memory");
}
#define CP_COMMIT() asm volatile("cp.async.commit_group;" ::: "memory")
#define CP_WAIT2()  asm volatile("cp.async.wait_group 2;" ::: "memory")

// ---------------- prep: -0.5*||e||^2 ----------------
__global__ void enorm_kernel(const float* __restrict__ emb) {
    int k = blockIdx.x * blockDim.x + threadIdx.x;
    if (k < KCODES) {
        const float4* r = (const float4*)(emb + k * CDIM);
        float s = 0.f;
        #pragma unroll
        for (int i = 0; i < 16; i++) {
            float4 v = r[i];
            s += v.x * v.x + v.y * v.y + v.z * v.z + v.w * v.w;
        }
        g_nhn[k] = -0.5f * s;
    }
}

// ---------------- prep: split B into tf32 hi/lo, fragment order ----------------
// m16n8k8 col.B fragment: lane = (n&7)*4 + (c&3), reg = (c>>2)&1.
__global__ void bsplit_kernel(const float* __restrict__ emb) {
    int idx = blockIdx.x * 256 + threadIdx.x;    // 65536 = K*C
    int k = idx >> 6, c = idx & 63;
    float v = emb[idx];
    float h = tf32f(v);
    float l = tf32f(v - h);
    int ch = k >> 6, n = k & 63;
    int flat = ch * 4096 + ((c >> 3) * 8 + (n >> 3)) * 64
             + ((n & 7) * 4 + (c & 3)) * 2 + ((c >> 2) & 1);
    g_Bh[flat] = h;
    g_Bl[flat] = l;
}

// ---------------- main: tf32 3-pass mma GEMM + fused argmin ----------------
// grid 512, block 256 (8 warps). CTA: 256q x 1024 codes. Warp: 32q x 64k.
__global__ void __launch_bounds__(256, 1)
vq_mma_kernel(const float* __restrict__ x, const float* __restrict__ emb,
              float* __restrict__ idx_out) {
    extern __shared__ char smem[];
    float* smLo = (float*)(smem + SM_LO);       // [256][68] A-lo tile
    float* nhn  = (float*)(smem + SM_NHN);
    uint32_t sb = (uint32_t)__cvta_generic_to_shared(smem);

    int tid = threadIdx.x, wid = tid >> 5, lane = tid & 31;
    int gid = lane >> 2, tig = lane & 3;
    int q0 = blockIdx.x << 8;

    // prefetch B chunks 0..2 into ring stages 0..2
    #pragma unroll
    for (int pf = 0; pf < 3; pf++) {
        uint32_t dst = sb + SM_B + pf * 32768;
        const float* sh = g_Bh + pf * 4096;
        const float* sl = g_Bl + pf * 4096;
        #pragma unroll
        for (int i = 0; i < 4; i++) cp16(dst + tid * 16 + i * 4096, sh + tid * 4 + i * 1024);
        #pragma unroll
        for (int i = 0; i < 4; i++) cp16(dst + 16384 + tid * 16 + i * 4096, sl + tid * 4 + i * 1024);
        CP_COMMIT();
    }

    for (int i = tid; i < KCODES; i += 256) nhn[i] = g_nhn[i];

    // A-lo tile to smem [q][68] (coalesced LDG, computed split)
    const float* xg = x + (size_t)(q0 >> 12) * (CDIM * 4096) + (q0 & 4095);
    #pragma unroll 4
    for (int it = 0; it < 16; it++) {
        int idx = tid + (it << 8);
        int f4 = idx & 63, c = idx >> 6;
        float4 v = *(const float4*)(xg + c * 4096 + f4 * 4);
        int qb = f4 * 4;
        smLo[(qb + 0) * 68 + c] = v.x - tf32f(v.x);
        smLo[(qb + 1) * 68 + c] = v.y - tf32f(v.y);
        smLo[(qb + 2) * 68 + c] = v.z - tf32f(v.z);
        smLo[(qb + 3) * 68 + c] = v.w - tf32f(v.w);
    }

    // A-hi fragments, register-resident for all 16 chunks (reads L1/L2-hot x)
    uint32_t ahr[2][8][4];
    {
        int r = lane >> 2, cc = lane & 3;
        #pragma unroll
        for (int mi = 0; mi < 2; mi++) {
            int qb = wid * 32 + mi * 16 + r;
            #pragma unroll
            for (int ks = 0; ks < 8; ks++) {
                const float* p = xg + (size_t)(ks * 8 + cc) * 4096 + qb;
                ahr[mi][ks][0] = tf32h(p[0]);
                ahr[mi][ks][1] = tf32h(p[8]);
                ahr[mi][ks][2] = tf32h(p[4 * 4096]);
                ahr[mi][ks][3] = tf32h(p[4 * 4096 + 8]);
            }
        }
    }

    float best[2][2];
    int   bidx[2][2];
    #pragma unroll
    for (int mi = 0; mi < 2; mi++) {
        best[mi][0] = best[mi][1] = -3.0e38f;
        bidx[mi][0] = bidx[mi][1] = 0;
    }

    float acc[2][8][4];

    for (int ch = 0; ch < 16; ch++) {
        CP_WAIT2();
        __syncthreads();

        // prefetch ch+3 (overwrites stage consumed at ch-1; safe past this barrier)
        int pf = ch + 3;
        if (pf < 16) {
            uint32_t dst = sb + SM_B + (pf & 3) * 32768;
            const float* sh = g_Bh + pf * 4096;
            const float* sl = g_Bl + pf * 4096;
            #pragma unroll
            for (int i = 0; i < 4; i++) cp16(dst + tid * 16 + i * 4096, sh + tid * 4 + i * 1024);
            #pragma unroll
            for (int i = 0; i < 4; i++) cp16(dst + 16384 + tid * 16 + i * 4096, sl + tid * 4 + i * 1024);
        }
        CP_COMMIT();

        const char* bh = smem + SM_B + (ch & 3) * 32768;
        const char* bl = bh + 16384;

        #pragma unroll
        for (int mi = 0; mi < 2; mi++)
            #pragma unroll
            for (int ni = 0; ni < 8; ni++)
                #pragma unroll
                for (int j = 0; j < 4; j++) acc[mi][ni][j] = 0.f;

        // pass 0: Ah x Bh     pass 1: Ah x Bl
        #pragma unroll
        for (int p = 0; p < 2; p++) {
            const char* bb = p ? bl : bh;
            #pragma unroll
            for (int ks = 0; ks < 8; ks++) {
                uint2 bf[8];
                #pragma unroll
                for (int ni = 0; ni < 8; ni++)
                    bf[ni] = *(const uint2*)(bb + (((ks * 8 + ni) * 32 + lane) << 3));
                #pragma unroll
                for (int mi = 0; mi < 2; mi++)
                    #pragma unroll
                    for (int ni = 0; ni < 8; ni++)
                        mma8(acc[mi][ni], ahr[mi][ks], (const uint32_t*)&bf[ni]);
            }
        }
        // pass 2: Al x Bh
        {
            int r = lane >> 2, cc = lane & 3;
            #pragma unroll
            for (int ks = 0; ks < 8; ks++) {
                uint32_t al[2][4];
                #pragma unroll
                for (int mi = 0; mi < 2; mi++) {
                    int qb = wid * 32 + mi * 16 + r;
                    int c0 = ks * 8 + cc;
                    al[mi][0] = __float_as_uint(smLo[qb * 68 + c0]);
                    al[mi][1] = __float_as_uint(smLo[(qb + 8) * 68 + c0]);
                    al[mi][2] = __float_as_uint(smLo[qb * 68 + c0 + 4]);
                    al[mi][3] = __float_as_uint(smLo[(qb + 8) * 68 + c0 + 4]);
                }
                uint2 bf[8];
                #pragma unroll
                for (int ni = 0; ni < 8; ni++)
                    bf[ni] = *(const uint2*)(bh + (((ks * 8 + ni) * 32 + lane) << 3));
                #pragma unroll
                for (int mi = 0; mi < 2; mi++)
                    #pragma unroll
                    for (int ni = 0; ni < 8; ni++)
                        mma8(acc[mi][ni], al[mi], (const uint32_t*)&bf[ni]);
            }
        }

        // fold -0.5||e||^2, running argmax (ascending k -> first-min tie-break)
        #pragma unroll
        for (int ni = 0; ni < 8; ni++) {
            float2 nn = *(const float2*)&nhn[ch * 64 + ni * 8 + tig * 2];
            int col = ch * 64 + ni * 8 + tig * 2;
            #pragma unroll
            for (int mi = 0; mi < 2; mi++) {
                float s;
                s = acc[mi][ni][0] + nn.x; if (s > best[mi][0]) { best[mi][0] = s; bidx[mi][0] = col; }
                s = acc[mi][ni][1] + nn.y; if (s > best[mi][0]) { best[mi][0] = s; bidx[mi][0] = col + 1; }
                s = acc[mi][ni][2] + nn.x; if (s > best[mi][1]) { best[mi][1] = s; bidx[mi][1] = col; }
                s = acc[mi][ni][3] + nn.y; if (s > best[mi][1]) { best[mi][1] = s; bidx[mi][1] = col + 1; }
            }
        }
    }

    // reduce across the 4 tig lanes sharing each query row
    #pragma unroll
    for (int mi = 0; mi < 2; mi++) {
        #pragma unroll
        for (int h = 0; h < 2; h++) {
            float s = best[mi][h];
            int   k = bidx[mi][h];
            #pragma unroll
            for (int off = 1; off <= 2; off <<= 1) {
                float so = __shfl_xor_sync(0xffffffffu, s, off);
                int   ko = __shfl_xor_sync(0xffffffffu, k, off);
                if (so > s || (so == s && ko < k)) { s = so; k = ko; }
            }
            if (tig == 0)
                idx_out[q0 + wid * 32 + mi * 16 + h * 8 + gid] = (float)k;
        }
    }
}

// ---------------- gather quantized + loss partials ----------------
__global__ void gather_kernel(const float* __restrict__ x,
                              const float* __restrict__ emb,
                              const float* __restrict__ idx_f,
                              float* __restrict__ outq) {
    int t  = blockIdx.x * 256 + threadIdx.x;
    int n  = t & (NQ - 1);
    int c0 = (t >> 17) << 2;
    int id = (int)idx_f[n];
    float4 ev = ((const float4*)emb)[id * 16 + (c0 >> 2)];
    int b = n >> 12, hw = n & 4095;
    int base = (b * 64 + c0) * 4096 + hw;
    float evs[4] = {ev.x, ev.y, ev.z, ev.w};
    float le = 0.f;
    #pragma unroll
    for (int j = 0; j < 4; j++) {
        int f = base + j * 4096;
        float xv = x[f];
        float d = evs[j] - xv;
        le += d * d;
        outq[f] = evs[j];
    }
    __shared__ float red[8];
    #pragma unroll
    for (int o = 16; o > 0; o >>= 1) le += __shfl_down_sync(0xffffffffu, le, o);
    if ((threadIdx.x & 31) == 0) red[threadIdx.x >> 5] = le;
    __syncthreads();
    if (threadIdx.x == 0) {
        float s = 0.f;
        #pragma unroll
        for (int w = 0; w < 8; w++) s += red[w];
        g_partials[blockIdx.x] = s;
    }
}

// ---------------- final deterministic loss reduce ----------------
__global__ void loss_kernel(float* __restrict__ out_loss) {
    __shared__ float smr[256];
    float s = 0.f;
    for (int i = threadIdx.x; i < 8192; i += 256) s += g_partials[i];
    smr[threadIdx.x] = s;
    __syncthreads();
    for (int o = 128; o > 0; o >>= 1) {
        if (threadIdx.x < o) smr[threadIdx.x] += smr[threadIdx.x + o];
        __syncthreads();
    }
    if (threadIdx.x == 0) out_loss[0] = 0.25f * smr[0] / 8388608.0f;
}

// ---------------- launch ----------------
extern "C" void kernel_launch(void* const* d_in, const int* in_sizes, int n_in,
                              void* d_out, int out_size) {
    const float* x   = (const float*)d_in[0];
    const float* emb = (const float*)d_in[1];
    if (n_in >= 2 && in_sizes[0] == KCODES * CDIM) {
        const float* t = x; x = emb; emb = t;
    }

    float* out      = (float*)d_out;
    float* out_loss = out;
    float* out_q    = out + 1;
    float* out_idx  = out + 1 + QTOT;

    cudaFuncSetAttribute((const void*)vq_mma_kernel,
                         cudaFuncAttributeMaxDynamicSharedMemorySize, SMEM_BYTES);

    bsplit_kernel<<<256, 256>>>(emb);
    enorm_kernel<<<4, 256>>>(emb);
    vq_mma_kernel<<<NQ / 256, 256, SMEM_BYTES>>>(x, emb, out_idx);
    gather_kernel<<<8192, 256>>>(x, emb, out_idx, out_q);
    loss_kernel<<<1, 256>>>(out_loss);
}

// round 7
// speedup vs baseline: 1.2393x; 1.0503x over previous
#include <cuda_runtime.h>
#include <cstdint>

#define NQ     131072
#define CDIM   64
#define KCODES 1024
#define QTOT   8388608

__device__ float g_nhn[KCODES];
__device__ float g_partials[8192];
// interleaved fragment-order codebook: per chunk (16) x [ks*8+ni] (64) x lane (32)
// x {h_reg0, h_reg1, l_reg0, l_reg1}
__device__ float g_B[131072];

// ---- smem layout (bytes): lo-tile [q][68] | B ring 4*32KB | nhn ----
#define SM_LO   0
#define SM_B    69632
#define SM_NHN  200704
#define SMEM_BYTES 204800

__device__ __forceinline__ uint32_t tf32h(float x) {
    uint32_t r; asm("cvt.rna.tf32.f32 %0, %1;" : "=r"(r) : "f"(x)); return r;
}
__device__ __forceinline__ float tf32f(float x) {
    return __uint_as_float(tf32h(x));
}
__device__ __forceinline__ void mma8(float* c, const uint32_t* a, uint32_t b0, uint32_t b1) {
    asm volatile("mma.sync.aligned.m16n8k8.row.col.f32.tf32.tf32.f32 "
        "{%0,%1,%2,%3}, {%4,%5,%6,%7}, {%8,%9}, {%0,%1,%2,%3};"
        : "+f"(c[0]), "+f"(c[1]), "+f"(c[2]), "+f"(c[3])
        : "r"(a[0]), "r"(a[1]), "r"(a[2]), "r"(a[3]), "r"(b0), "r"(b1));
}
__device__ __forceinline__ void cp16(uint32_t dst, const void* src) {
    asm volatile("cp.async.cg.shared.global [%0], [%1], 16;" :: "r"(dst), "l"(src) : "memory");
}
#define CP_COMMIT() asm volatile("cp.async.commit_group;" ::: "memory")
#define CP_WAIT2()  asm volatile("cp.async.wait_group 2;" ::: "memory")

// ---------------- prep: -0.5*||e||^2 ----------------
__global__ void enorm_kernel(const float* __restrict__ emb) {
    int k = blockIdx.x * blockDim.x + threadIdx.x;
    if (k < KCODES) {
        const float4* r = (const float4*)(emb + k * CDIM);
        float s = 0.f;
        #pragma unroll
        for (int i = 0; i < 16; i++) {
            float4 v = r[i];
            s += v.x * v.x + v.y * v.y + v.z * v.z + v.w * v.w;
        }
        g_nhn[k] = -0.5f * s;
    }
}

// ---------------- prep: split B into tf32 hi/lo, interleaved fragment order ----
// m16n8k8 col B fragment: lane = (n&7)*4 + (c&3), reg = (c>>2)&1, ks = c>>3.
__global__ void bsplit_kernel(const float* __restrict__ emb) {
    int idx = blockIdx.x * 256 + threadIdx.x;    // 65536 = K*C
    int k = idx >> 6, c = idx & 63;
    float v = emb[idx];
    float h = tf32f(v);
    float l = tf32f(v - h);
    int ch = k >> 6, ni = (k >> 3) & 7;
    int lane = ((k & 7) << 2) | (c & 3);
    int r = (c >> 2) & 1, ks = c >> 3;
    int flat4 = ch * 8192 + ((ks << 3) + ni) * 128 + lane * 4;
    g_B[flat4 + r]     = h;
    g_B[flat4 + 2 + r] = l;
}

// profiling-slot spacer (ncu captures the 4th launch in the stream)
__global__ void dummy_kernel() {}

// ---------------- main: fused tf32 3-term mma GEMM + argmin ----------------
// grid 512, block 256 (8 warps). CTA: 256q x 1024 codes. Warp: 32q x 64k.
__global__ void __launch_bounds__(256, 1)
vq_mma_kernel(const float* __restrict__ x, const float* __restrict__ emb,
              float* __restrict__ idx_out) {
    extern __shared__ char smem[];
    float* smLo = (float*)(smem + SM_LO);       // [256][68] A-lo tile
    float* nhn  = (float*)(smem + SM_NHN);
    uint32_t sb = (uint32_t)__cvta_generic_to_shared(smem);

    int tid = threadIdx.x, wid = tid >> 5, lane = tid & 31;
    int gid = lane >> 2, tig = lane & 3;
    int q0 = blockIdx.x << 8;

    // prefetch B chunks 0..2 into ring stages 0..2 (32KB each)
    #pragma unroll
    for (int pf = 0; pf < 3; pf++) {
        uint32_t dst = sb + SM_B + pf * 32768;
        const float* s = g_B + pf * 8192;
        #pragma unroll
        for (int i = 0; i < 8; i++) cp16(dst + tid * 16 + i * 4096, s + tid * 4 + i * 1024);
        CP_COMMIT();
    }

    for (int i = tid; i < KCODES; i += 256) nhn[i] = g_nhn[i];

    // A-lo tile to smem [q][68] (coalesced LDG, computed split)
    const float* xg = x + (size_t)(q0 >> 12) * (CDIM * 4096) + (q0 & 4095);
    #pragma unroll 4
    for (int it = 0; it < 16; it++) {
        int idx = tid + (it << 8);
        int f4 = idx & 63, c = idx >> 6;
        float4 v = *(const float4*)(xg + c * 4096 + f4 * 4);
        int qb = f4 * 4;
        smLo[(qb + 0) * 68 + c] = v.x - tf32f(v.x);
        smLo[(qb + 1) * 68 + c] = v.y - tf32f(v.y);
        smLo[(qb + 2) * 68 + c] = v.z - tf32f(v.z);
        smLo[(qb + 3) * 68 + c] = v.w - tf32f(v.w);
    }

    // A-hi fragments, register-resident for all 16 chunks
    uint32_t ahr[2][8][4];
    {
        int r = lane >> 2, cc = lane & 3;
        #pragma unroll
        for (int mi = 0; mi < 2; mi++) {
            int qb = wid * 32 + mi * 16 + r;
            #pragma unroll
            for (int ks = 0; ks < 8; ks++) {
                const float* p = xg + (size_t)(ks * 8 + cc) * 4096 + qb;
                ahr[mi][ks][0] = tf32h(p[0]);
                ahr[mi][ks][1] = tf32h(p[8]);
                ahr[mi][ks][2] = tf32h(p[4 * 4096]);
                ahr[mi][ks][3] = tf32h(p[4 * 4096 + 8]);
            }
        }
    }

    float best[2][2];
    int   bidx[2][2];
    #pragma unroll
    for (int mi = 0; mi < 2; mi++) {
        best[mi][0] = best[mi][1] = -3.0e38f;
        bidx[mi][0] = bidx[mi][1] = 0;
    }

    float acc[2][8][4];

    for (int ch = 0; ch < 16; ch++) {
        CP_WAIT2();
        __syncthreads();

        int pf = ch + 3;
        if (pf < 16) {
            uint32_t dst = sb + SM_B + (pf & 3) * 32768;
            const float* s = g_B + pf * 8192;
            #pragma unroll
            for (int i = 0; i < 8; i++) cp16(dst + tid * 16 + i * 4096, s + tid * 4 + i * 1024);
        }
        CP_COMMIT();

        const char* bb = smem + SM_B + (ch & 3) * 32768;

        #pragma unroll
        for (int mi = 0; mi < 2; mi++)
            #pragma unroll
            for (int ni = 0; ni < 8; ni++)
                #pragma unroll
                for (int j = 0; j < 4; j++) acc[mi][ni][j] = 0.f;

        int r = lane >> 2, cc = lane & 3;
        #pragma unroll
        for (int ks = 0; ks < 8; ks++) {
            // A-lo fragments for this ks (conflict-free: bank = 4r+cc)
            uint32_t al[2][4];
            #pragma unroll
            for (int mi = 0; mi < 2; mi++) {
                int qb = wid * 32 + mi * 16 + r;
                int c0 = ks * 8 + cc;
                al[mi][0] = __float_as_uint(smLo[qb * 68 + c0]);
                al[mi][1] = __float_as_uint(smLo[(qb + 8) * 68 + c0]);
                al[mi][2] = __float_as_uint(smLo[qb * 68 + c0 + 4]);
                al[mi][3] = __float_as_uint(smLo[(qb + 8) * 68 + c0 + 4]);
            }
            // B fragments: one LDS.128 per ni gives {h0,h1,l0,l1}
            #pragma unroll
            for (int nb = 0; nb < 2; nb++) {
                uint4 w[4];
                #pragma unroll
                for (int nj = 0; nj < 4; nj++)
                    w[nj] = *(const uint4*)(bb + (((ks * 8 + nb * 4 + nj) * 32 + lane) << 4));
                #pragma unroll
                for (int nj = 0; nj < 4; nj++) {
                    int ni = nb * 4 + nj;
                    #pragma unroll
                    for (int mi = 0; mi < 2; mi++) {
                        mma8(acc[mi][ni], ahr[mi][ks], w[nj].x, w[nj].y);  // hh
                        mma8(acc[mi][ni], ahr[mi][ks], w[nj].z, w[nj].w);  // h*l
                        mma8(acc[mi][ni], al[mi],      w[nj].x, w[nj].y);  // l*h
                    }
                }
            }
        }

        // fold -0.5||e||^2, running argmax (ascending k -> first-min tie-break)
        #pragma unroll
        for (int ni = 0; ni < 8; ni++) {
            float2 nn = *(const float2*)&nhn[ch * 64 + ni * 8 + tig * 2];
            int col = ch * 64 + ni * 8 + tig * 2;
            #pragma unroll
            for (int mi = 0; mi < 2; mi++) {
                float s;
                s = acc[mi][ni][0] + nn.x; if (s > best[mi][0]) { best[mi][0] = s; bidx[mi][0] = col; }
                s = acc[mi][ni][1] + nn.y; if (s > best[mi][0]) { best[mi][0] = s; bidx[mi][0] = col + 1; }
                s = acc[mi][ni][2] + nn.x; if (s > best[mi][1]) { best[mi][1] = s; bidx[mi][1] = col; }
                s = acc[mi][ni][3] + nn.y; if (s > best[mi][1]) { best[mi][1] = s; bidx[mi][1] = col + 1; }
            }
        }
    }

    // reduce across the 4 tig lanes sharing each query row
    #pragma unroll
    for (int mi = 0; mi < 2; mi++) {
        #pragma unroll
        for (int h = 0; h < 2; h++) {
            float s = best[mi][h];
            int   k = bidx[mi][h];
            #pragma unroll
            for (int off = 1; off <= 2; off <<= 1) {
                float so = __shfl_xor_sync(0xffffffffu, s, off);
                int   ko = __shfl_xor_sync(0xffffffffu, k, off);
                if (so > s || (so == s && ko < k)) { s = so; k = ko; }
            }
            if (tig == 0)
                idx_out[q0 + wid * 32 + mi * 16 + h * 8 + gid] = (float)k;
        }
    }
}

// ---------------- gather quantized + loss partials ----------------
__global__ void gather_kernel(const float* __restrict__ x,
                              const float* __restrict__ emb,
                              const float* __restrict__ idx_f,
                              float* __restrict__ outq) {
    int t  = blockIdx.x * 256 + threadIdx.x;
    int n  = t & (NQ - 1);
    int c0 = (t >> 17) << 2;
    int id = (int)idx_f[n];
    float4 ev = ((const float4*)emb)[id * 16 + (c0 >> 2)];
    int b = n >> 12, hw = n & 4095;
    int base = (b * 64 + c0) * 4096 + hw;
    float evs[4] = {ev.x, ev.y, ev.z, ev.w};
    float le = 0.f;
    #pragma unroll
    for (int j = 0; j < 4; j++) {
        int f = base + j * 4096;
        float xv = x[f];
        float d = evs[j] - xv;
        le += d * d;
        outq[f] = evs[j];
    }
    __shared__ float red[8];
    #pragma unroll
    for (int o = 16; o > 0; o >>= 1) le += __shfl_down_sync(0xffffffffu, le, o);
    if ((threadIdx.x & 31) == 0) red[threadIdx.x >> 5] = le;
    __syncthreads();
    if (threadIdx.x == 0) {
        float s = 0.f;
        #pragma unroll
        for (int w = 0; w < 8; w++) s += red[w];
        g_partials[blockIdx.x] = s;
    }
}

// ---------------- final deterministic loss reduce ----------------
__global__ void loss_kernel(float* __restrict__ out_loss) {
    __shared__ float smr[256];
    float s = 0.f;
    for (int i = threadIdx.x; i < 8192; i += 256) s += g_partials[i];
    smr[threadIdx.x] = s;
    __syncthreads();
    for (int o = 128; o > 0; o >>= 1) {
        if (threadIdx.x < o) smr[threadIdx.x] += smr[threadIdx.x + o];
        __syncthreads();
    }
    if (threadIdx.x == 0) out_loss[0] = 0.25f * smr[0] / 8388608.0f;
}

// ---------------- launch ----------------
extern "C" void kernel_launch(void* const* d_in, const int* in_sizes, int n_in,
                              void* d_out, int out_size) {
    const float* x   = (const float*)d_in[0];
    const float* emb = (const float*)d_in[1];
    if (n_in >= 2 && in_sizes[0] == KCODES * CDIM) {
        const float* t = x; x = emb; emb = t;
    }

    float* out      = (float*)d_out;
    float* out_loss = out;
    float* out_q    = out + 1;
    float* out_idx  = out + 1 + QTOT;

    cudaFuncSetAttribute((const void*)vq_mma_kernel,
                         cudaFuncAttributeMaxDynamicSharedMemorySize, SMEM_BYTES);

    bsplit_kernel<<<256, 256>>>(emb);
    enorm_kernel<<<4, 256>>>(emb);
    dummy_kernel<<<1, 32>>>();                 // shifts vq_mma into ncu's capture slot
    vq_mma_kernel<<<NQ / 256, 256, SMEM_BYTES>>>(x, emb, out_idx);
    gather_kernel<<<8192, 256>>>(x, emb, out_idx, out_q);
    loss_kernel<<<1, 256>>>(out_loss);
}